// round 7
// baseline (speedup 1.0000x reference)
#include <cuda_runtime.h>
#include <stdint.h>

#define TT 64          // num types
#define CC 128         // channels
#define TC (TT * CC)   // 8192 stat entries
#define NBLK 148       // one block per SM
#define WPB  12        // warps per block (3 streams x 4 quarters)
#define SPQ  3         // streams per quarter per block
#define NSTR (NBLK * SPQ)  // 444 streams per quarter
#define BR   8         // rows per batch

// ---- device scratch (no allocations allowed) ----
__device__ float2 g_scratch[NBLK * TC];   // per-block partial sums (9.4 MB)
__device__ float  g_cnt[TT];
__device__ float  g_mean[TC];
__device__ float  g_rstd[TC];
__device__ int    g_is64;

static __device__ __forceinline__ uint32_t smem_u32(const void* p) {
    uint32_t a;
    asm("{ .reg .u64 t; cvta.to.shared.u64 t, %1; cvt.u32.u64 %0, t; }"
        : "=r"(a) : "l"(p));
    return a;
}

// ---------------------------------------------------------------------------
// Kernel 0: zero counts + detect int64-vs-int32 type_vec encoding.
// int64 values 0..63 little-endian -> every odd int32 word == 0.
// ---------------------------------------------------------------------------
__global__ void k_init(const void* __restrict__ tv, long long n) {
    int idx = blockIdx.x * blockDim.x + threadIdx.x;
    if (idx < TT) g_cnt[idx] = 0.f;
    if (idx == 0) {
        const int* p = (const int*)tv;
        int lim = (n >= 256) ? 256 : (int)n;
        int is64 = 1;
        for (int i = 1; i < lim; i += 2)
            if (p[i] != 0) { is64 = 0; break; }
        g_is64 = is64;
    }
}

// ---------------------------------------------------------------------------
// Kernel 1: warp-private quarter-channel accumulation.
//   Warp w = (quarter q = w&3, stream j = w>>2). Each warp owns a PRIVATE
//   16KB table (64 types x 32 channels x float2) -> race-free by construction,
//   12 independent streams per SM. x staged through cp.async double buffers
//   (decouples DRAM latency from the register scoreboard). Flush: block-level
//   smem reduction then plain STG to g_scratch (no global atomics).
//   smem: 12*16KB tables + 12*2KB staging = 216KB. 1 block/SM.
// ---------------------------------------------------------------------------
__global__ void __launch_bounds__(384, 1) k_acc(
    const float* __restrict__ x, const void* __restrict__ tv, long long N)
{
    extern __shared__ char sm[];
    const int tid  = threadIdx.x;
    const int w    = tid >> 5;
    const int lane = tid & 31;
    const int q    = w & 3;        // channel quarter (columns q*32 .. q*32+31)
    const int j    = w >> 2;       // stream within quarter (0..2)

    float2* tbl = (float2*)(sm + w * 16384);            // 2048 float2 entries
    char*   stg = sm + WPB * 16384 + w * 2048;          // two 1KB buffers
    const uint32_t stg_base = smem_u32(stg);

    // Zero this warp's private table (no syncthreads needed: warp-private).
    #pragma unroll
    for (int i = lane; i < 2048; i += 32) tbl[i] = make_float2(0.f, 0.f);

    const int is64 = g_is64;
    const long long* __restrict__ tv64 = (const long long*)tv;
    const int*       __restrict__ tv32 = (const int*)tv;

    const int sq = blockIdx.x * SPQ + j;          // global stream id (quarter q)
    const long long batch_rows = (long long)NSTR * BR;
    const int nb = (int)((N + batch_rows - 1) / batch_rows);

    // --- helpers -----------------------------------------------------------
    // tv prefetch: lanes 0..7 hold types of rows r0..r0+7 (-1 past end)
#define LOADTY(DST, K) do {                                               \
        DST = -1;                                                          \
        if (lane < BR) {                                                   \
            long long rr = ((long long)sq + (long long)(K) * NSTR) * BR + lane; \
            if (rr < N) DST = is64 ? (int)tv64[rr] : tv32[rr];             \
        }                                                                  \
    } while (0)

    // cp.async 8 rows x 128B of quarter q into buffer (K&1):
    // two warp-ops of 4 rows each, 16B per lane.
#define ISSUE(K) do {                                                     \
        long long r0_ = ((long long)sq + (long long)(K) * NSTR) * BR;     \
        uint32_t dst_ = stg_base + ((K) & 1) * 1024                        \
                        + (lane >> 3) * 128 + (lane & 7) * 16;             \
        long long ra_ = r0_ + (lane >> 3);                                 \
        if (ra_ < N) {                                                     \
            const char* s_ = (const char*)x + (ra_ * CC + q * 32) * 4      \
                             + (lane & 7) * 16;                            \
            asm volatile("cp.async.ca.shared.global [%0], [%1], 16;"      \
                         :: "r"(dst_), "l"(s_));                           \
        }                                                                  \
        long long rb_ = ra_ + 4;                                           \
        if (rb_ < N) {                                                     \
            const char* s_ = (const char*)x + (rb_ * CC + q * 32) * 4      \
                             + (lane & 7) * 16;                            \
            asm volatile("cp.async.ca.shared.global [%0], [%1], 16;"      \
                         :: "r"(dst_ + 512), "l"(s_));                     \
        }                                                                  \
        asm volatile("cp.async.commit_group;");                            \
    } while (0)

    int c0 = 0, c1 = 0;   // register type counts (quarter-0 warps only)

#define RMW(BUF, TYR) do {                                                \
        const float* sx_ = (const float*)(stg + (BUF) * 1024);            \
        _Pragma("unroll")                                                  \
        for (int u = 0; u < BR; u++) {                                     \
            int t_u = __shfl_sync(0xffffffffu, TYR, u);                    \
            if (t_u >= 0) {                                                \
                float xf = sx_[u * 32 + lane];                             \
                int   o  = t_u * 32 + lane;                                \
                float2 a = tbl[o];                                         \
                a.x += xf;                                                 \
                a.y += xf * xf;                                            \
                tbl[o] = a;                                                \
                if (q == 0) {                                              \
                    c0 += (t_u == lane);                                   \
                    c1 += (t_u == lane + 32);                              \
                }                                                          \
            }                                                              \
        }                                                                  \
    } while (0)
    // -----------------------------------------------------------------------

    int ty0, ty1;
    LOADTY(ty0, 0);
    LOADTY(ty1, 1);
    ISSUE(0);
    ISSUE(1);

    for (int k = 0; k < nb; k++) {
        asm volatile("cp.async.wait_group 1;" ::: "memory");   // batch k ready
        if (k & 1) {
            RMW(1, ty1);
            LOADTY(ty1, k + 2);
        } else {
            RMW(0, ty0);
            LOADTY(ty0, k + 2);
        }
        ISSUE(k + 2);   // refill the buffer just consumed (same parity)
    }

#undef LOADTY
#undef ISSUE
#undef RMW

    __syncthreads();

    // Block reduction: sum the 3 streams of each quarter, store partials.
    for (int e = tid; e < TC; e += 384) {
        int t = e >> 7, c = e & 127;
        int qq = c >> 5, col = c & 31;
        float2 s = make_float2(0.f, 0.f);
        #pragma unroll
        for (int jj = 0; jj < SPQ; jj++) {
            const float2* tb = (const float2*)(sm + (qq + jj * 4) * 16384);
            float2 a = tb[t * 32 + col];
            s.x += a.x;
            s.y += a.y;
        }
        g_scratch[(long long)blockIdx.x * TC + e] = s;
    }

    // Counts: quarter-0 warps cover every row exactly once.
    if (q == 0) {
        if (c0) atomicAdd(&g_cnt[lane],      (float)c0);
        if (c1) atomicAdd(&g_cnt[lane + 32], (float)c1);
    }
}

// ---------------------------------------------------------------------------
// Kernel 2: reduce 148 block partials per entry, finalize mean / rstd
// (cnt clamped >= 1, var clamped >= 0, std = sqrt(var + 1e-5)).
// ---------------------------------------------------------------------------
__global__ void k_fin() {
    int e = blockIdx.x * blockDim.x + threadIdx.x;
    if (e >= TC) return;
    float s = 0.f, s2 = 0.f;
    #pragma unroll 4
    for (int b = 0; b < NBLK; b++) {
        float2 a = g_scratch[(long long)b * TC + e];
        s  += a.x;
        s2 += a.y;
    }
    float cnt  = fmaxf(g_cnt[e >> 7], 1.f);
    float mean = s / cnt;
    float var  = fmaxf(s2 / cnt - mean * mean, 0.f);
    g_mean[e] = mean;
    g_rstd[e] = 1.f / sqrtf(var + 1e-5f);
}

// ---------------------------------------------------------------------------
// Kernel 3: normalize (DRAM-bound at ~6.3 TB/s; unchanged from best round).
// Warp-per-row, float4 loads/stores, stats staged in shared as SEPARATE
// mean/rstd tables (conflict-free LDS.128). blockDim = 512.
// ---------------------------------------------------------------------------
#define NRM_U 4
__global__ void __launch_bounds__(512) k_norm(
    const float* __restrict__ x, const void* __restrict__ tv,
    float* __restrict__ out, long long N)
{
    extern __shared__ float smn[];
    float* smean = smn;        // TC
    float* srstd = smn + TC;   // TC
    const int tid = threadIdx.x;

    #pragma unroll
    for (int i = tid; i < TC; i += 512) {
        smean[i] = g_mean[i];
        srstd[i] = g_rstd[i];
    }
    __syncthreads();

    const int is64 = g_is64;
    const long long* __restrict__ tv64 = (const long long*)tv;
    const int*       __restrict__ tv32 = (const int*)tv;

    const int lane = tid & 31;
    const long long w  = (long long)blockIdx.x * 16 + (tid >> 5);
    const long long nw = (long long)gridDim.x * 16;
    const float4* __restrict__ x4 = (const float4*)x;
    float4* __restrict__ o4 = (float4*)out;

    for (long long r0 = w * NRM_U; r0 < N; r0 += nw * NRM_U) {
        float4 xv[NRM_U];
        int    ty[NRM_U];

        #pragma unroll
        for (int u = 0; u < NRM_U; u++) {
            long long r = r0 + u;
            if (r < N) {
                ty[u] = is64 ? (int)tv64[r] : tv32[r];
                xv[u] = x4[r * (CC / 4) + lane];
            } else ty[u] = -1;
        }
        #pragma unroll
        for (int u = 0; u < NRM_U; u++) {
            if (ty[u] >= 0) {
                int o = ty[u] * CC + 4 * lane;
                float4 mn = *(const float4*)&smean[o];
                float4 rs = *(const float4*)&srstd[o];
                float4 res;
                res.x = (xv[u].x - mn.x) * rs.x;
                res.y = (xv[u].y - mn.y) * rs.y;
                res.z = (xv[u].z - mn.z) * rs.z;
                res.w = (xv[u].w - mn.w) * rs.w;
                o4[(r0 + u) * (CC / 4) + lane] = res;
            }
        }
    }
}

// ---------------------------------------------------------------------------
// Launch
// ---------------------------------------------------------------------------
extern "C" void kernel_launch(void* const* d_in, const int* in_sizes, int n_in,
                              void* d_out, int out_size)
{
    const float* x  = (const float*)d_in[0];
    const void*  tv = d_in[1];
    float* out = (float*)d_out;
    const long long N = (long long)in_sizes[1];   // rows (type_vec length)

    const int ACC_SMEM = WPB * 16384 + WPB * 2048;    // 216 KB
    const int NRM_SMEM = 2 * TC * (int)sizeof(float); // 64 KB

    cudaFuncSetAttribute(k_acc,  cudaFuncAttributeMaxDynamicSharedMemorySize, ACC_SMEM);
    cudaFuncSetAttribute(k_norm, cudaFuncAttributeMaxDynamicSharedMemorySize, NRM_SMEM);

    k_init<<<1, 256>>>(tv, N);
    k_acc <<<NBLK, 384, ACC_SMEM>>>(x, tv, N);   // 1 block/SM, 12 streams/SM
    k_fin <<<32, 256>>>();
    k_norm<<<444, 512, NRM_SMEM>>>(x, tv, out, N);
}

// round 8
// speedup vs baseline: 1.5353x; 1.5353x over previous
#include <cuda_runtime.h>
#include <stdint.h>

#define TT 64          // num types
#define CC 128         // channels
#define TC (TT * CC)   // 8192 stat entries
#define MAXN (1 << 21) // max rows (N = 1e6 fits)
#define GH 444         // grid for hist/scatter/gather

// ---- device scratch (no allocations allowed) ----
__device__ int   g_perm[MAXN];        // rows sorted by type (8 MB)
__device__ int   g_typecnt[TT];
__device__ int   g_blockoff[GH * TT]; // per-block within-type offsets
__device__ int   g_typestart[TT + 1];
__device__ float g_sum[TC];
__device__ float g_sum2[TC];
__device__ float g_cnt[TT];
__device__ float g_mean[TC];
__device__ float g_rstd[TC];
__device__ int   g_is64;

// ---------------------------------------------------------------------------
// Kernel 0: zero accumulators + detect int64-vs-int32 type_vec encoding.
// int64 values 0..63 little-endian -> every odd int32 word == 0.
// ---------------------------------------------------------------------------
__global__ void k_init(const void* __restrict__ tv, long long n) {
    int idx = blockIdx.x * blockDim.x + threadIdx.x;
    if (idx < TC) { g_sum[idx] = 0.f; g_sum2[idx] = 0.f; }
    if (idx < TT) g_typecnt[idx] = 0;
    if (idx == 0) {
        const int* p = (const int*)tv;
        int lim = (n >= 256) ? 256 : (int)n;
        int is64 = 1;
        for (int i = 1; i < lim; i += 2)
            if (p[i] != 0) { is64 = 0; break; }
        g_is64 = is64;
    }
}

// ---------------------------------------------------------------------------
// Kernel 1: per-block histogram; capture this block's within-type base.
// ---------------------------------------------------------------------------
__global__ void __launch_bounds__(256) k_hist(
    const void* __restrict__ tv, long long N)
{
    __shared__ int hist[TT];
    const int tid = threadIdx.x;
    if (tid < TT) hist[tid] = 0;
    __syncthreads();

    const int is64 = g_is64;
    const long long* __restrict__ tv64 = (const long long*)tv;
    const int*       __restrict__ tv32 = (const int*)tv;

    const long long chunk = (N + GH - 1) / GH;
    const long long lo = (long long)blockIdx.x * chunk;
    const long long hi = (lo + chunk < N) ? lo + chunk : N;
    for (long long i = lo + tid; i < hi; i += 256) {
        int t = is64 ? (int)tv64[i] : tv32[i];
        atomicAdd(&hist[t], 1);
    }
    __syncthreads();
    if (tid < TT)
        g_blockoff[blockIdx.x * TT + tid] = atomicAdd(&g_typecnt[tid], hist[tid]);
}

// ---------------------------------------------------------------------------
// Kernel 2: exclusive prefix over 64 type counts (+ float counts for k_fin).
// ---------------------------------------------------------------------------
__global__ void k_prefix() {
    if (threadIdx.x == 0) {
        int acc = 0;
        for (int t = 0; t < TT; t++) {
            g_typestart[t] = acc;
            acc += g_typecnt[t];
            g_cnt[t] = (float)g_typecnt[t];
        }
        g_typestart[TT] = acc;
    }
}

// ---------------------------------------------------------------------------
// Kernel 3: scatter row indices into type-sorted order.
// Same block chunking as k_hist; smem rank counters reproduce H's counts.
// ---------------------------------------------------------------------------
__global__ void __launch_bounds__(256) k_scatter(
    const void* __restrict__ tv, long long N)
{
    __shared__ int srank[TT];
    __shared__ int sbase[TT];
    const int tid = threadIdx.x;
    if (tid < TT) {
        srank[tid] = 0;
        sbase[tid] = g_typestart[tid] + g_blockoff[blockIdx.x * TT + tid];
    }
    __syncthreads();

    const int is64 = g_is64;
    const long long* __restrict__ tv64 = (const long long*)tv;
    const int*       __restrict__ tv32 = (const int*)tv;

    const long long chunk = (N + GH - 1) / GH;
    const long long lo = (long long)blockIdx.x * chunk;
    const long long hi = (lo + chunk < N) ? lo + chunk : N;
    for (long long i = lo + tid; i < hi; i += 256) {
        int t = is64 ? (int)tv64[i] : tv32[i];
        int r = atomicAdd(&srank[t], 1);
        g_perm[sbase[t] + r] = (int)i;
    }
}

// ---------------------------------------------------------------------------
// Kernel 4: gather-accumulate. Warp-per-row over perm (type-sorted), lane l
// owns channels [4l,4l+4). REGISTER float4 sum/sumsq — no smem RMW chain.
// Type derived from perm position; flush via atomicAdd only at type
// boundaries / range end (~2 flushes per warp). Perm prefetched 1 batch
// ahead; 8 LDG.128 per warp in flight -> DRAM-bound.
// ---------------------------------------------------------------------------
#define CW 8
__global__ void __launch_bounds__(256) k_gather(
    const float* __restrict__ x, long long N)
{
    __shared__ int st[TT + 1];
    const int tid  = threadIdx.x;
    const int lane = tid & 31;
    for (int i = tid; i < TT + 1; i += 256) st[i] = g_typestart[i];
    __syncthreads();

    const long long nwarps = (long long)GH * 8;
    const long long gw  = (long long)blockIdx.x * 8 + (tid >> 5);
    const long long per = (N + nwarps - 1) / nwarps;
    const long long a = gw * per;
    const long long b = (a + per < N) ? a + per : N;
    if (a >= b) return;

    int t = 0;
    while (st[t + 1] <= (int)a) t++;
    int nxt = st[t + 1];

    float4 s = make_float4(0.f, 0.f, 0.f, 0.f);
    float4 q = make_float4(0.f, 0.f, 0.f, 0.f);
    const float4* __restrict__ x4 = (const float4*)x;

#define FLUSH() do {                                                      \
        if (q.x + q.y + q.z + q.w != 0.f) {                               \
            int base_ = t * CC + 4 * lane;                                \
            atomicAdd(&g_sum[base_ + 0], s.x);                            \
            atomicAdd(&g_sum[base_ + 1], s.y);                            \
            atomicAdd(&g_sum[base_ + 2], s.z);                            \
            atomicAdd(&g_sum[base_ + 3], s.w);                            \
            atomicAdd(&g_sum2[base_ + 0], q.x);                           \
            atomicAdd(&g_sum2[base_ + 1], q.y);                           \
            atomicAdd(&g_sum2[base_ + 2], q.z);                           \
            atomicAdd(&g_sum2[base_ + 3], q.w);                           \
            s = make_float4(0.f, 0.f, 0.f, 0.f);                          \
            q = make_float4(0.f, 0.f, 0.f, 0.f);                          \
        }                                                                  \
    } while (0)

    int rrA[CW];
    #pragma unroll
    for (int u = 0; u < CW; u++)
        rrA[u] = (a + u < b) ? g_perm[a + u] : 0;

    for (long long i = a; i < b; i += CW) {
        // prefetch next batch's perm (covered by this batch's x loads)
        int rrB[CW];
        const long long i2 = i + CW;
        #pragma unroll
        for (int u = 0; u < CW; u++)
            rrB[u] = (i2 + u < b) ? g_perm[i2 + u] : 0;

        const int m = (int)((b - i < CW) ? (b - i) : CW);
        float4 xv[CW];
        #pragma unroll
        for (int u = 0; u < CW; u++)
            if (u < m) xv[u] = x4[(long long)rrA[u] * (CC / 4) + lane];

        #pragma unroll
        for (int u = 0; u < CW; u++) {
            if (u < m) {
                const int idx = (int)(i + u);
                if (idx >= nxt) {            // type boundary (rare)
                    FLUSH();
                    do { t++; } while (st[t + 1] <= idx);
                    nxt = st[t + 1];
                }
                s.x += xv[u].x; s.y += xv[u].y;
                s.z += xv[u].z; s.w += xv[u].w;
                q.x = fmaf(xv[u].x, xv[u].x, q.x);
                q.y = fmaf(xv[u].y, xv[u].y, q.y);
                q.z = fmaf(xv[u].z, xv[u].z, q.z);
                q.w = fmaf(xv[u].w, xv[u].w, q.w);
            }
        }
        #pragma unroll
        for (int u = 0; u < CW; u++) rrA[u] = rrB[u];
    }
    FLUSH();
#undef FLUSH
}

// ---------------------------------------------------------------------------
// Kernel 5: finalize mean / rstd (cnt clamped >= 1, var clamped >= 0,
// std = sqrt(var + 1e-5)) — matches the reference exactly.
// ---------------------------------------------------------------------------
__global__ void k_fin() {
    int e = blockIdx.x * blockDim.x + threadIdx.x;
    if (e >= TC) return;
    float cnt  = fmaxf(g_cnt[e >> 7], 1.f);
    float mean = g_sum[e] / cnt;
    float var  = fmaxf(g_sum2[e] / cnt - mean * mean, 0.f);
    g_mean[e] = mean;
    g_rstd[e] = 1.f / sqrtf(var + 1e-5f);
}

// ---------------------------------------------------------------------------
// Kernel 6: normalize (at the LTS cap ~6.3 TB/s; unchanged best design).
// Warp-per-row, float4 loads/stores, stats staged in shared as SEPARATE
// mean/rstd tables (conflict-free LDS.128). blockDim = 512.
// ---------------------------------------------------------------------------
#define NRM_U 4
__global__ void __launch_bounds__(512) k_norm(
    const float* __restrict__ x, const void* __restrict__ tv,
    float* __restrict__ out, long long N)
{
    extern __shared__ float smn[];
    float* smean = smn;        // TC
    float* srstd = smn + TC;   // TC
    const int tid = threadIdx.x;

    #pragma unroll
    for (int i = tid; i < TC; i += 512) {
        smean[i] = g_mean[i];
        srstd[i] = g_rstd[i];
    }
    __syncthreads();

    const int is64 = g_is64;
    const long long* __restrict__ tv64 = (const long long*)tv;
    const int*       __restrict__ tv32 = (const int*)tv;

    const int lane = tid & 31;
    const long long w  = (long long)blockIdx.x * 16 + (tid >> 5);
    const long long nw = (long long)gridDim.x * 16;
    const float4* __restrict__ x4 = (const float4*)x;
    float4* __restrict__ o4 = (float4*)out;

    for (long long r0 = w * NRM_U; r0 < N; r0 += nw * NRM_U) {
        float4 xv[NRM_U];
        int    ty[NRM_U];

        #pragma unroll
        for (int u = 0; u < NRM_U; u++) {
            long long r = r0 + u;
            if (r < N) {
                ty[u] = is64 ? (int)tv64[r] : tv32[r];
                xv[u] = x4[r * (CC / 4) + lane];
            } else ty[u] = -1;
        }
        #pragma unroll
        for (int u = 0; u < NRM_U; u++) {
            if (ty[u] >= 0) {
                int o = ty[u] * CC + 4 * lane;
                float4 mn = *(const float4*)&smean[o];
                float4 rs = *(const float4*)&srstd[o];
                float4 res;
                res.x = (xv[u].x - mn.x) * rs.x;
                res.y = (xv[u].y - mn.y) * rs.y;
                res.z = (xv[u].z - mn.z) * rs.z;
                res.w = (xv[u].w - mn.w) * rs.w;
                o4[(r0 + u) * (CC / 4) + lane] = res;
            }
        }
    }
}

// ---------------------------------------------------------------------------
// Launch
// ---------------------------------------------------------------------------
extern "C" void kernel_launch(void* const* d_in, const int* in_sizes, int n_in,
                              void* d_out, int out_size)
{
    const float* x  = (const float*)d_in[0];
    const void*  tv = d_in[1];
    float* out = (float*)d_out;
    const long long N = (long long)in_sizes[1];   // rows (type_vec length)

    const int NRM_SMEM = 2 * TC * (int)sizeof(float); // 64 KB
    cudaFuncSetAttribute(k_norm, cudaFuncAttributeMaxDynamicSharedMemorySize, NRM_SMEM);

    k_init   <<<32, 256>>>(tv, N);
    k_hist   <<<GH, 256>>>(tv, N);
    k_prefix <<<1, 32>>>();
    k_scatter<<<GH, 256>>>(tv, N);
    k_gather <<<GH, 256>>>(x, N);
    k_fin    <<<32, 256>>>();
    k_norm   <<<444, 512, NRM_SMEM>>>(x, tv, out, N);
}